// round 7
// baseline (speedup 1.0000x reference)
#include <cuda_runtime.h>
#include <cuda_fp16.h>
#include <cstdint>

// ============================================================================
// Hopf CPG step via mma.sync (HMMA tf32, baseline PTX).
//   sin(psi_j - psi_i - phi_ij) = (s_j c_i - c_j s_i)cosφ - (c_j c_i + s_j s_i)sinφ
//   A = w_zd cosφ, B = w_zd sinφ, x = r·s, y = r·c
//   P = A x - B y, Q = A y + B x,  psi_dot_i = 2πV·σ(v_i) + c_i P_i - s_i Q_i
// Per 64-row tile: Z=[x|y] (64x64), W=[[Aᵀ,Bᵀ],[-Bᵀ,Aᵀ]] held COMPACT as
// AB[k][n]={A[n][k],B[n][k]} (32x32 float2); quadrant select/sign is
// compile-time per MMA step. One tile per CTA, grid=1024, 6 CTAs/SM.
// ============================================================================

#define PI2F 6.28318530717958647692f
#define ZS   68     // Z row stride (floats): A-frag bank = 4g+tig, conflict-free
#define AS   33     // AB row stride (float2)
#define SCS  34     // SC row stride (uints, even for uint2 loads)

__device__ __forceinline__ float tf32r(float x) {
    float r;
    asm("cvt.rna.tf32.f32 %0, %1;" : "=f"(r) : "f"(x));
    return r;
}
__device__ __forceinline__ float fsigmoid(float x) { return 1.0f / (1.0f + __expf(-x)); }

#define MMA_TF32(d, a0,a1,a2,a3, b0,b1) \
    asm volatile("mma.sync.aligned.m16n8k8.row.col.f32.tf32.tf32.f32 " \
        "{%0,%1,%2,%3}, {%4,%5,%6,%7}, {%8,%9}, {%0,%1,%2,%3};" \
        : "+f"((d)[0]), "+f"((d)[1]), "+f"((d)[2]), "+f"((d)[3]) \
        : "r"(a0), "r"(a1), "r"(a2), "r"(a3), \
          "r"(__float_as_uint(b0)), "r"(__float_as_uint(b1)))

// dynamic smem float layout
#define SM_Z     0                       // 64 x 68            = 4352
#define SM_AB    4352                    // 32 x 33 float2     = 2112
#define SM_SC    6464                    // 64 x 34 uint       = 2176
#define SM_TPV   8640                    // 32
#define SM_BA    8672                    // 32
#define SM_CA    8704                    // 32
#define SM_FLOATS 8736                   // 34944 bytes

__global__ __launch_bounds__(128, 6)
void hopf_mma(const float* __restrict__ in, float* __restrict__ out,
              const float* __restrict__ v, const float* __restrict__ b,
              const float* __restrict__ c, const float* __restrict__ w,
              const float* __restrict__ phi, int nrows) {
    extern __shared__ float sm[];
    float*    Z  = sm + SM_Z;
    float2*   AB = (float2*)(sm + SM_AB);
    uint32_t* SC = (uint32_t*)(sm + SM_SC);

    const int tid  = threadIdx.x;
    const int wid  = tid >> 5;
    const int lane = tid & 31;
    const int g    = lane >> 2;   // 0..7
    const int tig  = lane & 3;    // 0..3
    const int rowBase = blockIdx.x * 64;

    // ---- per-oscillator activations ----
    if (tid < 32) {
        sm[SM_TPV + tid] = (PI2F * 5.0f) * fsigmoid(v[tid]);
        sm[SM_BA  + tid] = 2.0f  * fsigmoid(b[tid]);
        sm[SM_CA  + tid] = 10.0f * fsigmoid(c[tid]);
    }

    // ---- compact AB tile: AB[j*AS + i] = {A[i][j], B[i][j]} (tf32-rounded) ----
    #pragma unroll
    for (int e = 0; e < 8; e++) {
        int m = tid + e * 128;            // flat i*32+j
        float A = 0.0f, Bv = 0.0f;
        if (m % 33 != 0) {                // zero-diag
            int kk = m / 33, jj = m % 33 - 1;
            float wa = fsigmoid(w[kk * 32 + jj]);            // W_MAX=1
            float pa = PI2F * fsigmoid(phi[kk * 32 + jj]);   // PHI_MAX=2pi
            float sp, cp;
            __sincosf(pa, &sp, &cp);
            A = tf32r(wa * cp);  Bv = tf32r(wa * sp);
        }
        int i = m >> 5, j = m & 31;
        AB[j * AS + i] = make_float2(A, Bv);
    }

    // ---- prologue: 16 elements/thread, coalesced (each warp owns whole rows) ----
    #pragma unroll
    for (int s = 0; s < 16; s++) {
        int e = tid + s * 128;
        int rl = e >> 5, ln = e & 31;
        int row = rowBase + rl;
        float psi = 0.0f, rr = 0.0f, rd = 0.0f;
        if (row < nrows) {
            const float* rp = in + (size_t)row * 96;
            psi = rp[ln];  rr = rp[32 + ln];  rd = rp[64 + ln];
        }
        float sv, cv;
        __sincosf(psi, &sv, &cv);
        Z[rl * ZS + ln]      = tf32r(rr * sv);   // x
        Z[rl * ZS + 32 + ln] = tf32r(rr * cv);   // y
        __half2 h = __floats2half2_rn(cv, sv);   // lo=c, hi=s
        SC[rl * SCS + ln] = *(uint32_t*)&h;
        if (row < nrows) {
            float ba = sm[SM_BA + ln], ca = sm[SM_CA + ln];
            float rdd = ca * (0.25f * ca * (ba - rr) - rd);
            float* op = out + (size_t)row * 96;
            op[32 + ln] = rd;
            op[64 + ln] = rdd;
        }
    }
    __syncthreads();

    // ---- MMA: warp owns 16 rows; accP = P n-tiles 0..3, accQ = Q n-tiles ----
    const int mrow = wid * 16;
    float accP[4][4], accQ[4][4];
    #pragma unroll
    for (int ntl = 0; ntl < 4; ntl++)
        #pragma unroll
        for (int q = 0; q < 4; q++) { accP[ntl][q] = 0.0f; accQ[ntl][q] = 0.0f; }

    #pragma unroll
    for (int kt = 0; kt < 8; kt++) {
        const int k0 = kt * 8;
        const int kk0 = (k0 & 31) + tig;         // compact k index (b0)
        const bool kq = (kt >= 4);               // k-quadrant (compile-time)
        uint32_t a0 = __float_as_uint(Z[(mrow + g)     * ZS + k0 + tig]);
        uint32_t a1 = __float_as_uint(Z[(mrow + g + 8) * ZS + k0 + tig]);
        uint32_t a2 = __float_as_uint(Z[(mrow + g)     * ZS + k0 + tig + 4]);
        uint32_t a3 = __float_as_uint(Z[(mrow + g + 8) * ZS + k0 + tig + 4]);
        #pragma unroll
        for (int ntl = 0; ntl < 4; ntl++) {
            int nn = ntl * 8 + g;
            float2 ab0 = AB[kk0 * AS + nn];      // shared by P and Q tiles
            float2 ab1 = AB[(kk0 + 4) * AS + nn];
            // W quadrants: (k<32,n<32)=A  (k<32,n>=32)=B  (k>=32,n<32)=-B  (k>=32,n>=32)=A
            float b0p = kq ? -ab0.y : ab0.x;
            float b1p = kq ? -ab1.y : ab1.x;
            float b0q = kq ?  ab0.x : ab0.y;
            float b1q = kq ?  ab1.x : ab1.y;
            MMA_TF32(accP[ntl], a0, a1, a2, a3, b0p, b1p);
            MMA_TF32(accQ[ntl], a0, a1, a2, a3, b0q, b1q);
        }
    }

    // ---- epilogue: psi_dot = tpv + c*P - s*Q, bounce into Z cols 0..31 ----
    const float2* tpv2 = (const float2*)(sm + SM_TPV);
    #pragma unroll
    for (int ntl = 0; ntl < 4; ntl++) {
        int col = ntl * 8 + 2 * tig;             // even, 8B-aligned pair
        float2 tp = tpv2[col >> 1];
        #pragma unroll
        for (int rs = 0; rs < 2; rs++) {         // rows g, g+8
            int rl = mrow + g + rs * 8;
            uint2 hh = *(const uint2*)&SC[rl * SCS + col];
            __half2 h0 = *(__half2*)&hh.x, h1 = *(__half2*)&hh.y;
            float c0 = __low2float(h0), s0 = __high2float(h0);
            float c1 = __low2float(h1), s1 = __high2float(h1);
            float2 pd;
            pd.x = tp.x + c0 * accP[ntl][rs * 2]     - s0 * accQ[ntl][rs * 2];
            pd.y = tp.y + c1 * accP[ntl][rs * 2 + 1] - s1 * accQ[ntl][rs * 2 + 1];
            *(float2*)&Z[rl * ZS + col] = pd;
        }
    }
    __syncthreads();

    // ---- coalesced psi_dot copy-out ----
    #pragma unroll
    for (int s = 0; s < 16; s++) {
        int e = tid + s * 128;
        int rl = e >> 5, ln = e & 31;
        int row = rowBase + rl;
        if (row < nrows) out[(size_t)row * 96 + ln] = Z[rl * ZS + ln];
    }
}

extern "C" void kernel_launch(void* const* d_in, const int* in_sizes, int n_in,
                              void* d_out, int out_size) {
    const float* states = (const float*)d_in[0];
    const float* v      = (const float*)d_in[1];
    const float* b      = (const float*)d_in[2];
    const float* c      = (const float*)d_in[3];
    const float* w      = (const float*)d_in[4];
    const float* phi    = (const float*)d_in[5];
    float* out = (float*)d_out;

    const int nrows  = in_sizes[0] / 96;          // 65536
    const int ntiles = (nrows + 63) / 64;         // 1024

    cudaFuncSetAttribute(hopf_mma, cudaFuncAttributeMaxDynamicSharedMemorySize,
                         SM_FLOATS * 4);
    hopf_mma<<<ntiles, 128, SM_FLOATS * 4>>>(states, out, v, b, c, w, phi, nrows);
}

// round 8
// speedup vs baseline: 1.0577x; 1.0577x over previous
#include <cuda_runtime.h>

// Hopf oscillator CPG step, reformulated:
//   sin(psi_j - psi_i - phi_ij) = (s_j c_i - c_j s_i)cosφ - (c_j c_i + s_j s_i)sinφ
// A_ij = w_zd cosφ_zd, B_ij = w_zd sinφ_zd, x_j = r_j s_j, y_j = r_j c_j:
//   coupling_i = c_i*(A x - B y)_i - s_i*(A y + B x)_i
// R8 = R2 (best: 25.8us) with occupancy fix: 128-thread CTAs x 2048, 8 CTAs/SM,
// and unguarded fast path for full 8-row warp tiles (65536 % 32 == 0).

#define PI2F 6.28318530717958647692f

typedef unsigned long long u64;

__device__ __forceinline__ u64 pack2(float lo, float hi) {
    u64 r;
    asm("mov.b64 %0, {%1, %2};" : "=l"(r) : "f"(lo), "f"(hi));
    return r;
}
__device__ __forceinline__ void unpack2(u64 v, float& lo, float& hi) {
    asm("mov.b64 {%0, %1}, %2;" : "=f"(lo), "=f"(hi) : "l"(v));
}
#define FMA2(acc, a, b) asm("fma.rn.f32x2 %0, %1, %2, %0;" : "+l"(acc) : "l"(a), "l"(b))

__device__ __forceinline__ float fsigmoid(float x) {
    return 1.0f / (1.0f + __expf(-x));
}

__global__ __launch_bounds__(128, 8)
void hopf_kernel(const float* __restrict__ in, float* __restrict__ out,
                 const float* __restrict__ v, const float* __restrict__ b,
                 const float* __restrict__ c, const float* __restrict__ w,
                 const float* __restrict__ phi, int nrows) {
    const int tid  = threadIdx.x;
    const int lane = tid & 31;          // oscillator index i
    const int wib  = tid >> 5;          // warp in block (0..3)
    const int gw   = blockIdx.x * 4 + wib;

    // sAB[j*32 + i] = {A[i][j], B[i][j]}  -> lane-consecutive LDS.64, conflict-free
    __shared__ float2 sAB[1024];
    __shared__ float4 sXY[4][2][32];    // per-warp {x0,x1,y0,y1} broadcast buffers

    // ---- build activation matrix in smem (8 entries per thread) ----
    #pragma unroll
    for (int k = 0; k < 8; k++) {
        int m = tid + k * 128;          // flat index, i = m/32, j = m%32
        float A = 0.0f, Bv = 0.0f;
        if (m % 33 != 0) {              // zero-diag: diagonal iff m % 33 == 0
            int kk = m / 33;            // 0..30
            int jj = m % 33 - 1;        // 0..31
            float wa = fsigmoid(w[kk * 32 + jj]);           // W_MAX = 1
            float pa = PI2F * fsigmoid(phi[kk * 32 + jj]);  // PHI_MAX = 2*pi
            float sp, cp;
            __sincosf(pa, &sp, &cp);
            A  = wa * cp;
            Bv = wa * sp;
        }
        sAB[(m & 31) * 32 + (m >> 5)] = make_float2(A, Bv);  // store [j][i]
    }

    // per-lane activations
    const float tpv = (PI2F * 5.0f) * fsigmoid(v[lane]);
    const float ba  = 2.0f  * fsigmoid(b[lane]);
    const float ca  = 10.0f * fsigmoid(c[lane]);

    __syncthreads();

    const int rowBase = gw * 8;         // 8 rows per warp, two 4-row quads
    const bool full = (rowBase + 8 <= nrows);

    #pragma unroll
    for (int q = 0; q < 2; q++) {
        const int r0 = rowBase + q * 4;
        float sv[4], cv[4], xv[4], yv[4];

        if (full) {
            // ---- unguarded fast path ----
            #pragma unroll
            for (int t = 0; t < 4; t++) {
                const float* rp = in + (size_t)(r0 + t) * 96;
                float psi = rp[lane];
                float rr  = rp[32 + lane];
                float rd  = rp[64 + lane];
                __sincosf(psi, &sv[t], &cv[t]);
                xv[t] = rr * sv[t];
                yv[t] = rr * cv[t];
                float rdd = ca * (0.25f * ca * (ba - rr) - rd);
                float* op = out + (size_t)(r0 + t) * 96;
                op[32 + lane] = rd;
                op[64 + lane] = rdd;
            }
        } else {
            #pragma unroll
            for (int t = 0; t < 4; t++) {
                const int row = r0 + t;
                float psi = 0.0f, rr = 0.0f, rd = 0.0f;
                if (row < nrows) {
                    const float* rp = in + (size_t)row * 96;
                    psi = rp[lane];
                    rr  = rp[32 + lane];
                    rd  = rp[64 + lane];
                }
                __sincosf(psi, &sv[t], &cv[t]);
                xv[t] = rr * sv[t];
                yv[t] = rr * cv[t];
                if (row < nrows) {
                    float rdd = ca * (0.25f * ca * (ba - rr) - rd);
                    float* op = out + (size_t)row * 96;
                    op[32 + lane] = rd;
                    op[64 + lane] = rdd;
                }
            }
        }

        __syncwarp();   // previous quad's readers done before overwrite
        sXY[wib][0][lane] = make_float4(xv[0], xv[1], yv[0], yv[1]);
        sXY[wib][1][lane] = make_float4(xv[2], xv[3], yv[2], yv[3]);
        __syncwarp();

        // accumulators: P1=sum(Ax), P2=sum(By), Q1=sum(Ay), Q2=sum(Bx)
        u64 aP1 = 0, aP2 = 0, aQ1 = 0, aQ2 = 0;   // rows (0,1)
        u64 bP1 = 0, bP2 = 0, bQ1 = 0, bQ2 = 0;   // rows (2,3)

        #pragma unroll
        for (int j = 0; j < 32; j++) {
            float2 ab = sAB[j * 32 + lane];        // LDS.64, conflict-free
            u64 AA = pack2(ab.x, ab.x);            // {A,A}
            u64 BB = pack2(ab.y, ab.y);            // {B,B}
            ulonglong2 p0 = *reinterpret_cast<const ulonglong2*>(&sXY[wib][0][j]);
            ulonglong2 p1 = *reinterpret_cast<const ulonglong2*>(&sXY[wib][1][j]);
            FMA2(aP1, AA, p0.x);  FMA2(aP2, BB, p0.y);
            FMA2(aQ1, AA, p0.y);  FMA2(aQ2, BB, p0.x);
            FMA2(bP1, AA, p1.x);  FMA2(bP2, BB, p1.y);
            FMA2(bQ1, AA, p1.y);  FMA2(bQ2, BB, p1.x);
        }

        float P[4], Q[4];
        {
            float l0,h0,l1,h1,l2,h2,l3,h3;
            unpack2(aP1,l0,h0); unpack2(aP2,l1,h1);
            unpack2(aQ1,l2,h2); unpack2(aQ2,l3,h3);
            P[0] = l0 - l1;  P[1] = h0 - h1;
            Q[0] = l2 + l3;  Q[1] = h2 + h3;
        }
        {
            float l0,h0,l1,h1,l2,h2,l3,h3;
            unpack2(bP1,l0,h0); unpack2(bP2,l1,h1);
            unpack2(bQ1,l2,h2); unpack2(bQ2,l3,h3);
            P[2] = l0 - l1;  P[3] = h0 - h1;
            Q[2] = l2 + l3;  Q[3] = h2 + h3;
        }

        if (full) {
            #pragma unroll
            for (int t = 0; t < 4; t++)
                out[(size_t)(r0 + t) * 96 + lane] = tpv + cv[t] * P[t] - sv[t] * Q[t];
        } else {
            #pragma unroll
            for (int t = 0; t < 4; t++) {
                const int row = r0 + t;
                if (row < nrows)
                    out[(size_t)row * 96 + lane] = tpv + cv[t] * P[t] - sv[t] * Q[t];
            }
        }
    }
}

extern "C" void kernel_launch(void* const* d_in, const int* in_sizes, int n_in,
                              void* d_out, int out_size) {
    const float* states = (const float*)d_in[0];
    const float* v      = (const float*)d_in[1];
    const float* b      = (const float*)d_in[2];
    const float* c      = (const float*)d_in[3];
    const float* w      = (const float*)d_in[4];
    const float* phi    = (const float*)d_in[5];
    float* out = (float*)d_out;

    const int nrows = in_sizes[0] / 96;     // 65536
    const int rows_per_warp = 8;
    const int warps  = (nrows + rows_per_warp - 1) / rows_per_warp;
    const int blocks = (warps + 3) / 4;     // 4 warps (128 threads) per block

    hopf_kernel<<<blocks, 128>>>(states, out, v, b, c, w, phi, nrows);
}

// round 9
// speedup vs baseline: 1.3500x; 1.2764x over previous
#include <cuda_runtime.h>

// Hopf oscillator CPG step, reformulated:
//   sin(psi_j - psi_i - phi_ij) = (s_j c_i - c_j s_i)cosφ - (c_j c_i + s_j s_i)sinφ
// A_ij = w_zd cosφ_zd, B_ij = w_zd sinφ_zd, x_j = r_j s_j, y_j = r_j c_j:
//   coupling_i = c_i*(A x - B y)_i - s_i*(A y + B x)_i
// R9 = R2 (best: 25.8us) + prep kernel: the 32x32 activation matrix is computed
// ONCE (tiny kernel) instead of redundantly per CTA; main CTAs copy it L2->smem.

#define PI2F 6.28318530717958647692f

typedef unsigned long long u64;

__device__ float2 gAB[1024];    // [j*32 + i] = {A[i][j], B[i][j]}  (pre-transposed)
__device__ float  gTPV[32];     // 2*pi*V_MAX*sigmoid(v)
__device__ float  gBA[32];      // B_MAX*sigmoid(b)
__device__ float  gCA[32];      // C_MAX*sigmoid(c)

__device__ __forceinline__ u64 pack2(float lo, float hi) {
    u64 r;
    asm("mov.b64 %0, {%1, %2};" : "=l"(r) : "f"(lo), "f"(hi));
    return r;
}
__device__ __forceinline__ void unpack2(u64 v, float& lo, float& hi) {
    asm("mov.b64 {%0, %1}, %2;" : "=f"(lo), "=f"(hi) : "l"(v));
}
#define FMA2(acc, a, b) asm("fma.rn.f32x2 %0, %1, %2, %0;" : "+l"(acc) : "l"(a), "l"(b))

__device__ __forceinline__ float fsigmoid(float x) {
    return 1.0f / (1.0f + __expf(-x));
}

__global__ void prep_kernel(const float* __restrict__ v, const float* __restrict__ b,
                            const float* __restrict__ c, const float* __restrict__ w,
                            const float* __restrict__ phi) {
    int m = threadIdx.x;            // 0..1023, m = i*32 + j
    float A = 0.0f, Bv = 0.0f;
    if (m % 33 != 0) {              // zero-diag: diagonal iff m % 33 == 0
        int kk = m / 33;            // 0..30
        int jj = m % 33 - 1;        // 0..31
        float wa = fsigmoid(w[kk * 32 + jj]);           // W_MAX = 1
        float pa = PI2F * fsigmoid(phi[kk * 32 + jj]);  // PHI_MAX = 2*pi
        float sp, cp;
        __sincosf(pa, &sp, &cp);
        A  = wa * cp;
        Bv = wa * sp;
    }
    gAB[(m & 31) * 32 + (m >> 5)] = make_float2(A, Bv);  // store [j][i]
    if (m < 32) {
        gTPV[m] = (PI2F * 5.0f) * fsigmoid(v[m]);
        gBA[m]  = 2.0f  * fsigmoid(b[m]);
        gCA[m]  = 10.0f * fsigmoid(c[m]);
    }
}

__global__ __launch_bounds__(256, 4)
void hopf_kernel(const float* __restrict__ in, float* __restrict__ out, int nrows) {
    const int tid  = threadIdx.x;
    const int lane = tid & 31;          // oscillator index i
    const int wib  = tid >> 5;          // warp in block (0..7)
    const int gw   = blockIdx.x * 8 + wib;

    __shared__ float2 sAB[1024];        // [j*32 + i], lane-consecutive LDS.64
    __shared__ float4 sXY[8][2][32];    // per-warp {x0,x1,y0,y1} broadcast buffers

    // ---- coalesced L2->smem copy of the prebuilt matrix (2 float4 per thread) ----
    {
        const float4* src = reinterpret_cast<const float4*>(gAB);
        float4*       dst = reinterpret_cast<float4*>(sAB);
        dst[tid]       = src[tid];
        dst[tid + 256] = src[tid + 256];
    }

    // per-lane activations (tiny, broadcast loads, L2-hot)
    const float tpv = gTPV[lane];
    const float ba  = gBA[lane];
    const float ca  = gCA[lane];

    __syncthreads();

    const int rowBase = gw * 8;         // 8 rows per warp, two 4-row quads
    const bool full = (rowBase + 8 <= nrows);

    #pragma unroll
    for (int q = 0; q < 2; q++) {
        const int r0 = rowBase + q * 4;
        float sv[4], cv[4], xv[4], yv[4];

        if (full) {
            #pragma unroll
            for (int t = 0; t < 4; t++) {
                const float* rp = in + (size_t)(r0 + t) * 96;
                float psi = rp[lane];
                float rr  = rp[32 + lane];
                float rd  = rp[64 + lane];
                __sincosf(psi, &sv[t], &cv[t]);
                xv[t] = rr * sv[t];
                yv[t] = rr * cv[t];
                float rdd = ca * (0.25f * ca * (ba - rr) - rd);
                float* op = out + (size_t)(r0 + t) * 96;
                op[32 + lane] = rd;
                op[64 + lane] = rdd;
            }
        } else {
            #pragma unroll
            for (int t = 0; t < 4; t++) {
                const int row = r0 + t;
                float psi = 0.0f, rr = 0.0f, rd = 0.0f;
                if (row < nrows) {
                    const float* rp = in + (size_t)row * 96;
                    psi = rp[lane];
                    rr  = rp[32 + lane];
                    rd  = rp[64 + lane];
                }
                __sincosf(psi, &sv[t], &cv[t]);
                xv[t] = rr * sv[t];
                yv[t] = rr * cv[t];
                if (row < nrows) {
                    float rdd = ca * (0.25f * ca * (ba - rr) - rd);
                    float* op = out + (size_t)row * 96;
                    op[32 + lane] = rd;
                    op[64 + lane] = rdd;
                }
            }
        }

        __syncwarp();   // previous quad's readers done before overwrite
        sXY[wib][0][lane] = make_float4(xv[0], xv[1], yv[0], yv[1]);
        sXY[wib][1][lane] = make_float4(xv[2], xv[3], yv[2], yv[3]);
        __syncwarp();

        // accumulators: P1=sum(Ax), P2=sum(By), Q1=sum(Ay), Q2=sum(Bx)
        u64 aP1 = 0, aP2 = 0, aQ1 = 0, aQ2 = 0;   // rows (0,1)
        u64 bP1 = 0, bP2 = 0, bQ1 = 0, bQ2 = 0;   // rows (2,3)

        #pragma unroll
        for (int j = 0; j < 32; j++) {
            float2 ab = sAB[j * 32 + lane];        // LDS.64, conflict-free
            u64 AA = pack2(ab.x, ab.x);            // {A,A}
            u64 BB = pack2(ab.y, ab.y);            // {B,B}
            ulonglong2 p0 = *reinterpret_cast<const ulonglong2*>(&sXY[wib][0][j]);
            ulonglong2 p1 = *reinterpret_cast<const ulonglong2*>(&sXY[wib][1][j]);
            FMA2(aP1, AA, p0.x);  FMA2(aP2, BB, p0.y);
            FMA2(aQ1, AA, p0.y);  FMA2(aQ2, BB, p0.x);
            FMA2(bP1, AA, p1.x);  FMA2(bP2, BB, p1.y);
            FMA2(bQ1, AA, p1.y);  FMA2(bQ2, BB, p1.x);
        }

        float P[4], Q[4];
        {
            float l0,h0,l1,h1,l2,h2,l3,h3;
            unpack2(aP1,l0,h0); unpack2(aP2,l1,h1);
            unpack2(aQ1,l2,h2); unpack2(aQ2,l3,h3);
            P[0] = l0 - l1;  P[1] = h0 - h1;
            Q[0] = l2 + l3;  Q[1] = h2 + h3;
        }
        {
            float l0,h0,l1,h1,l2,h2,l3,h3;
            unpack2(bP1,l0,h0); unpack2(bP2,l1,h1);
            unpack2(bQ1,l2,h2); unpack2(bQ2,l3,h3);
            P[2] = l0 - l1;  P[3] = h0 - h1;
            Q[2] = l2 + l3;  Q[3] = h2 + h3;
        }

        if (full) {
            #pragma unroll
            for (int t = 0; t < 4; t++)
                out[(size_t)(r0 + t) * 96 + lane] = tpv + cv[t] * P[t] - sv[t] * Q[t];
        } else {
            #pragma unroll
            for (int t = 0; t < 4; t++) {
                const int row = r0 + t;
                if (row < nrows)
                    out[(size_t)row * 96 + lane] = tpv + cv[t] * P[t] - sv[t] * Q[t];
            }
        }
    }
}

extern "C" void kernel_launch(void* const* d_in, const int* in_sizes, int n_in,
                              void* d_out, int out_size) {
    const float* states = (const float*)d_in[0];
    const float* v      = (const float*)d_in[1];
    const float* b      = (const float*)d_in[2];
    const float* c      = (const float*)d_in[3];
    const float* w      = (const float*)d_in[4];
    const float* phi    = (const float*)d_in[5];
    float* out = (float*)d_out;

    const int nrows = in_sizes[0] / 96;     // 65536
    prep_kernel<<<1, 1024>>>(v, b, c, w, phi);

    const int rows_per_warp = 8;
    const int warps  = (nrows + rows_per_warp - 1) / rows_per_warp;
    const int blocks = (warps + 7) / 8;     // 8 warps (256 threads) per block

    hopf_kernel<<<blocks, 256>>>(states, out, nrows);
}

// round 10
// speedup vs baseline: 1.3519x; 1.0014x over previous
#include <cuda_runtime.h>
#include <cuda_fp16.h>

// Hopf oscillator CPG step, reformulated:
//   sin(psi_j - psi_i - phi_ij) = (s_j c_i - c_j s_i)cosφ - (c_j c_i + s_j s_i)sinφ
// A_ij = w_zd cosφ_zd, B_ij = w_zd sinφ_zd, x_j = r_j s_j, y_j = r_j c_j:
//   coupling_i = c_i*(A x - B y)_i - s_i*(A y + B x)_i
// R10 = R9 (23.0us) with the matrix in fp16: sAB is __half2{A,B} -> inner-loop
// matrix load is LDS.32 (1 wavefront) instead of LDS.64 (2). |A|,|B| < 1 so the
// half rounding (4.9e-4 rel) contributes ~7e-5 to output norm rel_err.

#define PI2F 6.28318530717958647692f

typedef unsigned long long u64;

__device__ __half2 gABh[1024];  // [j*32 + i] = half2{A[i][j], B[i][j]} (pre-transposed)
__device__ float   gTPV[32];    // 2*pi*V_MAX*sigmoid(v)
__device__ float   gBA[32];     // B_MAX*sigmoid(b)
__device__ float   gCA[32];     // C_MAX*sigmoid(c)

__device__ __forceinline__ u64 pack2(float lo, float hi) {
    u64 r;
    asm("mov.b64 %0, {%1, %2};" : "=l"(r) : "f"(lo), "f"(hi));
    return r;
}
__device__ __forceinline__ void unpack2(u64 v, float& lo, float& hi) {
    asm("mov.b64 {%0, %1}, %2;" : "=f"(lo), "=f"(hi) : "l"(v));
}
#define FMA2(acc, a, b) asm("fma.rn.f32x2 %0, %1, %2, %0;" : "+l"(acc) : "l"(a), "l"(b))

__device__ __forceinline__ float fsigmoid(float x) {
    return 1.0f / (1.0f + __expf(-x));
}

__global__ void prep_kernel(const float* __restrict__ v, const float* __restrict__ b,
                            const float* __restrict__ c, const float* __restrict__ w,
                            const float* __restrict__ phi) {
    int m = threadIdx.x;            // 0..1023, m = i*32 + j
    float A = 0.0f, Bv = 0.0f;
    if (m % 33 != 0) {              // zero-diag: diagonal iff m % 33 == 0
        int kk = m / 33;            // 0..30
        int jj = m % 33 - 1;        // 0..31
        float wa = fsigmoid(w[kk * 32 + jj]);           // W_MAX = 1
        float pa = PI2F * fsigmoid(phi[kk * 32 + jj]);  // PHI_MAX = 2*pi
        float sp, cp;
        __sincosf(pa, &sp, &cp);
        A  = wa * cp;
        Bv = wa * sp;
    }
    gABh[(m & 31) * 32 + (m >> 5)] = __floats2half2_rn(A, Bv);  // store [j][i]
    if (m < 32) {
        gTPV[m] = (PI2F * 5.0f) * fsigmoid(v[m]);
        gBA[m]  = 2.0f  * fsigmoid(b[m]);
        gCA[m]  = 10.0f * fsigmoid(c[m]);
    }
}

__global__ __launch_bounds__(256, 4)
void hopf_kernel(const float* __restrict__ in, float* __restrict__ out, int nrows) {
    const int tid  = threadIdx.x;
    const int lane = tid & 31;          // oscillator index i
    const int wib  = tid >> 5;          // warp in block (0..7)
    const int gw   = blockIdx.x * 8 + wib;

    __shared__ __half2 sAB[1024];       // [j*32 + i], lane-consecutive LDS.32
    __shared__ float4  sXY[8][2][32];   // per-warp {x0,x1,y0,y1} broadcast buffers

    // ---- coalesced L2->smem copy of the prebuilt half2 matrix (4KB) ----
    {
        const float4* src = reinterpret_cast<const float4*>(gABh);
        float4*       dst = reinterpret_cast<float4*>(sAB);
        dst[tid] = src[tid];
    }

    // per-lane activations (broadcast loads, L2-hot)
    const float tpv = gTPV[lane];
    const float ba  = gBA[lane];
    const float ca  = gCA[lane];

    __syncthreads();

    const int rowBase = gw * 8;         // 8 rows per warp, two 4-row quads
    const bool full = (rowBase + 8 <= nrows);

    #pragma unroll
    for (int q = 0; q < 2; q++) {
        const int r0 = rowBase + q * 4;
        float sv[4], cv[4], xv[4], yv[4];

        if (full) {
            #pragma unroll
            for (int t = 0; t < 4; t++) {
                const float* rp = in + (size_t)(r0 + t) * 96;
                float psi = rp[lane];
                float rr  = rp[32 + lane];
                float rd  = rp[64 + lane];
                __sincosf(psi, &sv[t], &cv[t]);
                xv[t] = rr * sv[t];
                yv[t] = rr * cv[t];
                float rdd = ca * (0.25f * ca * (ba - rr) - rd);
                float* op = out + (size_t)(r0 + t) * 96;
                op[32 + lane] = rd;
                op[64 + lane] = rdd;
            }
        } else {
            #pragma unroll
            for (int t = 0; t < 4; t++) {
                const int row = r0 + t;
                float psi = 0.0f, rr = 0.0f, rd = 0.0f;
                if (row < nrows) {
                    const float* rp = in + (size_t)row * 96;
                    psi = rp[lane];
                    rr  = rp[32 + lane];
                    rd  = rp[64 + lane];
                }
                __sincosf(psi, &sv[t], &cv[t]);
                xv[t] = rr * sv[t];
                yv[t] = rr * cv[t];
                if (row < nrows) {
                    float rdd = ca * (0.25f * ca * (ba - rr) - rd);
                    float* op = out + (size_t)row * 96;
                    op[32 + lane] = rd;
                    op[64 + lane] = rdd;
                }
            }
        }

        __syncwarp();   // previous quad's readers done before overwrite
        sXY[wib][0][lane] = make_float4(xv[0], xv[1], yv[0], yv[1]);
        sXY[wib][1][lane] = make_float4(xv[2], xv[3], yv[2], yv[3]);
        __syncwarp();

        // accumulators: P1=sum(Ax), P2=sum(By), Q1=sum(Ay), Q2=sum(Bx)
        u64 aP1 = 0, aP2 = 0, aQ1 = 0, aQ2 = 0;   // rows (0,1)
        u64 bP1 = 0, bP2 = 0, bQ1 = 0, bQ2 = 0;   // rows (2,3)

        #pragma unroll
        for (int j = 0; j < 32; j++) {
            __half2 h = sAB[j * 32 + lane];        // LDS.32, conflict-free (1 wf)
            float Af = __low2float(h);
            float Bf = __high2float(h);
            u64 AA = pack2(Af, Af);                // {A,A}
            u64 BB = pack2(Bf, Bf);                // {B,B}
            ulonglong2 p0 = *reinterpret_cast<const ulonglong2*>(&sXY[wib][0][j]);
            ulonglong2 p1 = *reinterpret_cast<const ulonglong2*>(&sXY[wib][1][j]);
            FMA2(aP1, AA, p0.x);  FMA2(aP2, BB, p0.y);
            FMA2(aQ1, AA, p0.y);  FMA2(aQ2, BB, p0.x);
            FMA2(bP1, AA, p1.x);  FMA2(bP2, BB, p1.y);
            FMA2(bQ1, AA, p1.y);  FMA2(bQ2, BB, p1.x);
        }

        float P[4], Q[4];
        {
            float l0,h0,l1,h1,l2,h2,l3,h3;
            unpack2(aP1,l0,h0); unpack2(aP2,l1,h1);
            unpack2(aQ1,l2,h2); unpack2(aQ2,l3,h3);
            P[0] = l0 - l1;  P[1] = h0 - h1;
            Q[0] = l2 + l3;  Q[1] = h2 + h3;
        }
        {
            float l0,h0,l1,h1,l2,h2,l3,h3;
            unpack2(bP1,l0,h0); unpack2(bP2,l1,h1);
            unpack2(bQ1,l2,h2); unpack2(bQ2,l3,h3);
            P[2] = l0 - l1;  P[3] = h0 - h1;
            Q[2] = l2 + l3;  Q[3] = h2 + h3;
        }

        if (full) {
            #pragma unroll
            for (int t = 0; t < 4; t++)
                out[(size_t)(r0 + t) * 96 + lane] = tpv + cv[t] * P[t] - sv[t] * Q[t];
        } else {
            #pragma unroll
            for (int t = 0; t < 4; t++) {
                const int row = r0 + t;
                if (row < nrows)
                    out[(size_t)row * 96 + lane] = tpv + cv[t] * P[t] - sv[t] * Q[t];
            }
        }
    }
}

extern "C" void kernel_launch(void* const* d_in, const int* in_sizes, int n_in,
                              void* d_out, int out_size) {
    const float* states = (const float*)d_in[0];
    const float* v      = (const float*)d_in[1];
    const float* b      = (const float*)d_in[2];
    const float* c      = (const float*)d_in[3];
    const float* w      = (const float*)d_in[4];
    const float* phi    = (const float*)d_in[5];
    float* out = (float*)d_out;

    const int nrows = in_sizes[0] / 96;     // 65536
    prep_kernel<<<1, 1024>>>(v, b, c, w, phi);

    const int rows_per_warp = 8;
    const int warps  = (nrows + rows_per_warp - 1) / rows_per_warp;
    const int blocks = (warps + 7) / 8;     // 8 warps (256 threads) per block

    hopf_kernel<<<blocks, 256>>>(states, out, nrows);
}